// round 13
// baseline (speedup 1.0000x reference)
#include <cuda_runtime.h>
#include <cuda_fp16.h>
#include <cstdint>

// ---------------- problem constants ----------------
constexpr int B_    = 4;
constexpr int T_    = 16;
constexpr int HEADS = 8;
constexpr int HW    = 1024;       // 32*32
constexpr int NSLAB = B_ * T_;    // 64
constexpr float QSCALE = 0.17677669529663687f;

// ---------------- scratch (__device__ globals) ----------------
__device__ __half g_xhi[NSLAB * HW * 256];  // [slab][hw][c]
__device__ __half g_whi[768 * 256];         // [o][c]
__device__ __half g_wlo[768 * 256];
__device__ __half g_wohi[256 * 256];
__device__ __half g_q[B_ * HEADS * T_ * 32 * HW];  // fp16 [b][head][t][d][hw]
__device__ __half g_k[B_ * HEADS * T_ * 32 * HW];
__device__ __half g_v[B_ * HEADS * T_ * 32 * HW];
__device__ __half g_ohi[NSLAB * HW * 256];  // [slab][hw][e]

// ---------------- PTX helpers ----------------
__device__ __forceinline__ uint32_t smem_u32(const void* p) {
    uint32_t a;
    asm("{ .reg .u64 t; cvta.to.shared.u64 t, %1; cvt.u32.u64 %0, t; }" : "=r"(a) : "l"(p));
    return a;
}
__device__ __forceinline__ void cp16(uint32_t s, const void* g) {
    asm volatile("cp.async.cg.shared.global [%0], [%1], 16;" :: "r"(s), "l"(g) : "memory");
}
__device__ __forceinline__ void cp_commit() {
    asm volatile("cp.async.commit_group;" ::: "memory");
}
template <int N>
__device__ __forceinline__ void cp_wait() {
    asm volatile("cp.async.wait_group %0;" :: "n"(N) : "memory");
}
__device__ __forceinline__ void ldsm4(uint32_t& r0, uint32_t& r1, uint32_t& r2,
                                      uint32_t& r3, uint32_t a) {
    asm volatile("ldmatrix.sync.aligned.m8n8.x4.shared.b16 {%0,%1,%2,%3}, [%4];"
                 : "=r"(r0), "=r"(r1), "=r"(r2), "=r"(r3) : "r"(a));
}
__device__ __forceinline__ void mma16816(float& c0, float& c1, float& c2, float& c3,
                                         uint32_t a0, uint32_t a1, uint32_t a2,
                                         uint32_t a3, uint32_t b0, uint32_t b1) {
    asm volatile(
        "mma.sync.aligned.m16n8k16.row.col.f32.f16.f16.f32 "
        "{%0,%1,%2,%3}, {%4,%5,%6,%7}, {%8,%9}, {%0,%1,%2,%3};"
        : "+f"(c0), "+f"(c1), "+f"(c2), "+f"(c3)
        : "r"(a0), "r"(a1), "r"(a2), "r"(a3), "r"(b0), "r"(b1));
}

// ---------------- SMEM staging layout (swizzled, no padding) ----------------
constexpr int O_AHI = 0;
constexpr int O_BHI = 8192;
constexpr int O_BLO = 12288;
constexpr int STAGE = 16384;
constexpr int SMEM_TOTAL = 49152;           // 2 stages + epilogue headroom
constexpr int CSTR = 132;                   // C smem row stride (floats)

__device__ __forceinline__ uint32_t swz(int row, int chunk) {
    return (uint32_t)(row * 64 + ((chunk ^ ((row >> 1) & 3)) << 4));
}

// ================= tensor-core GEMM =================
// D[hw 128, o 64] = A[hw, K] * B[o, K]^T, K=256.
// PASSES==2: A_hi*(B_hi + B_lo). PASSES==1: plain fp16.
// EPI 0: q/k/v fp16 epilogue. EPI 1: +bias -> f32 Y.
// Occupancy probe: 5 CTAs/SM (reg budget 102).
template <int EPI, int PASSES>
__global__ __launch_bounds__(128, 5) void mma_gemm(const __half* __restrict__ Ahig,
                                                   const __half* __restrict__ Bhig,
                                                   const __half* __restrict__ Blog,
                                                   const float* __restrict__ bias,
                                                   float* __restrict__ Y) {
    extern __shared__ __align__(1024) char smem[];
    const uint32_t sb = smem_u32(smem);
    const int tid  = threadIdx.x;
    const int wid  = tid >> 5;
    const int lane = tid & 31;
    const int wm = wid & 1;     // warp m tile (64 rows)
    const int wn = wid >> 1;    // warp n tile (32 cols)

    const int slab = blockIdx.z;
    const int hw0  = blockIdx.x * 128;
    const int n0   = blockIdx.y * 64;

    const __half* ah = Ahig + ((size_t)slab * HW + hw0) * 256;
    const __half* bh = Bhig + (size_t)n0 * 256;
    const __half* bl = (PASSES == 2) ? Blog + (size_t)n0 * 256 : bh;

    const int rowA0 = wm * 64 + (lane & 15);
    const int chA   = lane >> 4;
    const int rowB  = wn * 32 + lane;
    const uint32_t adrA[4] = {
        sb + O_AHI + swz(rowA0,      chA),
        sb + O_AHI + swz(rowA0 + 16, chA),
        sb + O_AHI + swz(rowA0 + 32, chA),
        sb + O_AHI + swz(rowA0 + 48, chA)};
    const uint32_t adrB = sb + O_BHI + swz(rowB, 0);

    float acc[4][4][4];
#pragma unroll
    for (int mt = 0; mt < 4; mt++)
#pragma unroll
        for (int nt = 0; nt < 4; nt++)
#pragma unroll
            for (int r = 0; r < 4; r++) acc[mt][nt][r] = 0.0f;

    const int rA = tid >> 2, sA = tid & 3;
    const int rswIO = (rA >> 1) & 3;
    const uint32_t soIO = (uint32_t)(rA * 64 + ((sA ^ rswIO) << 4));

    auto issue = [&](int kt, int s) {
        const uint32_t base = sb + s * STAGE;
        const int kbase = kt * 32;
#pragma unroll
        for (int v = 0; v < 4; v++) {
            const uint32_t so = soIO + (uint32_t)(v * 2048);
            const size_t go = (size_t)(rA + 32 * v) * 256 + kbase + sA * 8;
            cp16(base + O_AHI + so, ah + go);
        }
#pragma unroll
        for (int v = 0; v < 2; v++) {
            const uint32_t so = soIO + (uint32_t)(v * 2048);
            const size_t go = (size_t)(rA + 32 * v) * 256 + kbase + sA * 8;
            cp16(base + O_BHI + so, bh + go);
            if (PASSES == 2) cp16(base + O_BLO + so, bl + go);
        }
    };

    issue(0, 0);
    cp_commit();

    uint32_t so = 0;
    for (int kt = 0; kt < 8; kt++) {
        if (kt < 7) {
            issue(kt + 1, (kt + 1) & 1);
            cp_commit();
            cp_wait<1>();
        } else {
            cp_wait<0>();
        }
        __syncthreads();

#pragma unroll
        for (int kk = 0; kk < 2; kk++) {
            const uint32_t kx = (uint32_t)(kk << 5);
            uint32_t ahi[4][4];
            uint32_t b0h[4], b1h[4];
#pragma unroll
            for (int mt = 0; mt < 4; mt++)
                ldsm4(ahi[mt][0], ahi[mt][1], ahi[mt][2], ahi[mt][3],
                      (adrA[mt] ^ kx) + so);
            const uint32_t bb = (adrB ^ kx) + so;
            ldsm4(b0h[0], b0h[1], b0h[2], b0h[3], bb);
            ldsm4(b1h[0], b1h[1], b1h[2], b1h[3], bb ^ 0x10);

            if (PASSES == 2) {
                uint32_t b0l[4], b1l[4];
                ldsm4(b0l[0], b0l[1], b0l[2], b0l[3], bb + 4096);
                ldsm4(b1l[0], b1l[1], b1l[2], b1l[3], (bb ^ 0x10) + 4096);
#pragma unroll
                for (int mt = 0; mt < 4; mt++)
#pragma unroll
                    for (int nt = 0; nt < 4; nt++)
                        mma16816(acc[mt][nt][0], acc[mt][nt][1], acc[mt][nt][2],
                                 acc[mt][nt][3], ahi[mt][0], ahi[mt][1],
                                 ahi[mt][2], ahi[mt][3], b0h[nt], b1h[nt]);
#pragma unroll
                for (int mt = 0; mt < 4; mt++)
#pragma unroll
                    for (int nt = 0; nt < 4; nt++)
                        mma16816(acc[mt][nt][0], acc[mt][nt][1], acc[mt][nt][2],
                                 acc[mt][nt][3], ahi[mt][0], ahi[mt][1],
                                 ahi[mt][2], ahi[mt][3], b0l[nt], b1l[nt]);
            } else {
#pragma unroll
                for (int mt = 0; mt < 4; mt++)
#pragma unroll
                    for (int nt = 0; nt < 4; nt++)
                        mma16816(acc[mt][nt][0], acc[mt][nt][1], acc[mt][nt][2],
                                 acc[mt][nt][3], ahi[mt][0], ahi[mt][1],
                                 ahi[mt][2], ahi[mt][3], b0h[nt], b1h[nt]);
            }
        }
        __syncthreads();
        so ^= (uint32_t)STAGE;
    }

    // ---------------- epilogue: transpose through SMEM ----------------
    float* cs = (float*)smem;   // [64 n][CSTR m]
#pragma unroll
    for (int mt = 0; mt < 4; mt++)
#pragma unroll
        for (int nt = 0; nt < 4; nt++) {
            const int n = wn * 32 + nt * 8 + (lane & 3) * 2;
            const int m = wm * 64 + mt * 16 + (lane >> 2);
            cs[n * CSTR + m]           = acc[mt][nt][0];
            cs[(n + 1) * CSTR + m]     = acc[mt][nt][1];
            cs[n * CSTR + m + 8]       = acc[mt][nt][2];
            cs[(n + 1) * CSTR + m + 8] = acc[mt][nt][3];
        }
    __syncthreads();

    const int b_ = slab >> 4, t_ = slab & 15;
#pragma unroll
    for (int r = 0; r < 16; r++) {
        const int n = wid * 16 + r;
        const int o = n0 + n;
        float4 v = *(const float4*)&cs[n * CSTR + lane * 4];
        const float bv = bias[o];
        if (EPI == 0) {
            const int which = o >> 8;
            const int head  = (o >> 5) & 7;
            const int d     = o & 31;
            __half* dst = (which == 0) ? g_q : (which == 1 ? g_k : g_v);
            const float sc = (which == 0) ? QSCALE : 1.0f;
            const __half2 h01 = __halves2half2(__float2half_rn((v.x + bv) * sc),
                                               __float2half_rn((v.y + bv) * sc));
            const __half2 h23 = __halves2half2(__float2half_rn((v.z + bv) * sc),
                                               __float2half_rn((v.w + bv) * sc));
            const size_t off =
                ((size_t)(((b_ * 8 + head) * 16 + t_) * 32 + d)) * 1024 + hw0 + lane * 4;
            uint2 pk;
            pk.x = *(const uint32_t*)&h01;
            pk.y = *(const uint32_t*)&h23;
            *(uint2*)(dst + off) = pk;
        } else {
            v.x += bv; v.y += bv; v.z += bv; v.w += bv;
            *(float4*)(Y + ((size_t)slab * 256 + o) * 1024 + hw0 + lane * 4) = v;
        }
    }
}

// ================= fused prep kernel =================
// blocks [0,768):    w_qkv hi/lo split (row = bid, 256 elems)
// blocks [768,1024): w_out fp16 convert
// blocks [1024,5120): x [slab][c][hw] -> g_xhi [slab][hw][c] fp16 (64x64 tiles)
__global__ __launch_bounds__(256) void prep_k(const float* __restrict__ w_qkv,
                                              const float* __restrict__ w_out,
                                              const float* __restrict__ x) {
    const int bid = blockIdx.x;
    const int tid = threadIdx.x;

    if (bid < 768) {
        const int i = bid * 256 + tid;
        const float f = w_qkv[i];
        const __half h = __float2half_rn(f);
        g_whi[i] = h;
        g_wlo[i] = __float2half_rn(f - __half2float(h));
        return;
    }
    if (bid < 1024) {
        const int i = (bid - 768) * 256 + tid;
        g_wohi[i] = __float2half_rn(w_out[i]);
        return;
    }

    __shared__ float ts[64][65];
    const int id = bid - 1024;
    const int h0 = (id & 15) * 64;
    const int c0 = ((id >> 4) & 3) * 64;
    const int slab = id >> 6;
    const int r = tid >> 2;
    const int q4 = tid & 3;

    const float* src = x + ((size_t)slab * 256 + c0 + r) * 1024 + h0 + q4 * 16;
#pragma unroll
    for (int j = 0; j < 4; j++) {
        const float4 v = *(const float4*)(src + j * 4);
        ts[r][q4 * 16 + j * 4 + 0] = v.x;
        ts[r][q4 * 16 + j * 4 + 1] = v.y;
        ts[r][q4 * 16 + j * 4 + 2] = v.z;
        ts[r][q4 * 16 + j * 4 + 3] = v.w;
    }
    __syncthreads();

    __half hb[16];
#pragma unroll
    for (int j = 0; j < 16; j++)
        hb[j] = __float2half_rn(ts[q4 * 16 + j][r]);
    const size_t o = ((size_t)slab * 1024 + h0 + r) * 256 + c0 + q4 * 16;
    *(uint4*)(g_xhi + o)     = ((uint4*)hb)[0];
    *(uint4*)(g_xhi + o + 8) = ((uint4*)hb)[1];
}

// ================= attention (T=16), fp16 in, fp16 out =================
__device__ __forceinline__ unsigned long long pack2(float lo, float hi) {
    unsigned long long r;
    asm("mov.b64 %0, {%1, %2};" : "=l"(r) : "f"(lo), "f"(hi));
    return r;
}
__device__ __forceinline__ void unpack2(unsigned long long p, float& lo, float& hi) {
    asm("mov.b64 {%0, %1}, %2;" : "=f"(lo), "=f"(hi) : "l"(p));
}
__device__ __forceinline__ unsigned long long ffma2(unsigned long long a,
                                                    unsigned long long b,
                                                    unsigned long long c) {
    unsigned long long d;
    asm("fma.rn.f32x2 %0, %1, %2, %3;" : "=l"(d) : "l"(a), "l"(b), "l"(c));
    return d;
}

constexpr int KVP = 516;
constexpr int ATTN_SMEM = 2 * 16 * KVP * 4;   // 66048 bytes

__global__ __launch_bounds__(256) void attn_k(const float* __restrict__ rel_pos) {
    extern __shared__ __align__(16) float asmem[];
    float* k_s = asmem;                 // [16][KVP]
    float* v_s = asmem + 16 * KVP;

    const int bh  = blockIdx.y;            // b*8 + head
    const int hw0 = blockIdx.x * 16;
    const int tid = threadIdx.x;
    const int hwl = tid & 15;
    const int i   = tid >> 4;              // query t 0..15

    const size_t ubase = (size_t)bh * 512 * HW;

#pragma unroll
    for (int it = 0; it < 4; it++) {
        const int slot = tid + 256 * it;   // 0..1023
        const int td  = slot >> 1;
        const int seg = (slot & 1) * 8;
        const size_t go = ubase + (size_t)td * HW + hw0 + seg;
        const uint4 rk = *(const uint4*)(g_k + go);
        const uint4 rv = *(const uint4*)(g_v + go);
        const __half2* hk = (const __half2*)&rk;
        const __half2* hv = (const __half2*)&rv;
#pragma unroll
        for (int c = 0; c < 4; c++) {
            const float2 fk = __half22float2(hk[c]);
            const float2 fv = __half22float2(hv[c]);
            k_s[(seg + 2 * c)     * KVP + td] = fk.x;
            k_s[(seg + 2 * c + 1) * KVP + td] = fk.y;
            v_s[(seg + 2 * c)     * KVP + td] = fv.x;
            v_s[(seg + 2 * c + 1) * KVP + td] = fv.y;
        }
    }
    __syncthreads();

    unsigned long long qp[16];
    const size_t qbase = ubase + (size_t)i * 32 * HW + hw0 + hwl;
#pragma unroll
    for (int c = 0; c < 16; c++)
        qp[c] = pack2(__half2float(g_q[qbase + (size_t)(2 * c) * HW]),
                      __half2float(g_q[qbase + (size_t)(2 * c + 1) * HW]));

    const int head = bh & 7;
    const float* rp = rel_pos + head * 256 + i * 16;

    float s[16];
#pragma unroll
    for (int j = 0; j < 16; j++) {
        const ulonglong2* kp = (const ulonglong2*)&k_s[hwl * KVP + j * 32];
        unsigned long long acc = 0ull;
#pragma unroll
        for (int c = 0; c < 8; c++) {
            const ulonglong2 kk = kp[c];
            acc = ffma2(qp[2 * c],     kk.x, acc);
            acc = ffma2(qp[2 * c + 1], kk.y, acc);
        }
        float lo, hi;
        unpack2(acc, lo, hi);
        s[j] = lo + hi + rp[j];
    }

    float mx = s[0];
#pragma unroll
    for (int j = 1; j < 16; j++) mx = fmaxf(mx, s[j]);
    float sum = 0.0f;
#pragma unroll
    for (int j = 0; j < 16; j++) { s[j] = expf(s[j] - mx); sum += s[j]; }
    const float inv = 1.0f / sum;

    unsigned long long o2[16];
#pragma unroll
    for (int c = 0; c < 16; c++) o2[c] = 0ull;
#pragma unroll
    for (int j = 0; j < 16; j++) {
        const unsigned long long pp = pack2(s[j], s[j]);
        const ulonglong2* vp = (const ulonglong2*)&v_s[hwl * KVP + j * 32];
#pragma unroll
        for (int c = 0; c < 8; c++) {
            const ulonglong2 vv = vp[c];
            o2[2 * c]     = ffma2(pp, vv.x, o2[2 * c]);
            o2[2 * c + 1] = ffma2(pp, vv.y, o2[2 * c + 1]);
        }
    }

    const int b_ = bh >> 3;
    const size_t obase =
        ((size_t)((b_ * 16 + i)) * 1024 + hw0 + hwl) * 256 + head * 32;
#pragma unroll
    for (int c = 0; c < 16; c++) {
        float lo, hi;
        unpack2(o2[c], lo, hi);
        ((__half2*)(g_ohi + obase))[c] =
            __halves2half2(__float2half_rn(lo * inv), __float2half_rn(hi * inv));
    }
}

// ================= host =================
extern "C" void kernel_launch(void* const* d_in, const int* in_sizes, int n_in,
                              void* d_out, int out_size) {
    const float* x       = (const float*)d_in[0];
    const float* rel_pos = (const float*)d_in[1];
    const float* w_qkv   = (const float*)d_in[2];
    const float* b_qkv   = (const float*)d_in[3];
    const float* w_out   = (const float*)d_in[4];
    const float* b_out   = (const float*)d_in[5];
    float* y = (float*)d_out;

    cudaFuncSetAttribute(mma_gemm<0, 2>, cudaFuncAttributeMaxDynamicSharedMemorySize, SMEM_TOTAL);
    cudaFuncSetAttribute(mma_gemm<1, 1>, cudaFuncAttributeMaxDynamicSharedMemorySize, SMEM_TOTAL);
    cudaFuncSetAttribute(attn_k, cudaFuncAttributeMaxDynamicSharedMemorySize, ATTN_SMEM);

    __half *xhi, *whi, *wlo, *wohi, *ohi;
    cudaGetSymbolAddress((void**)&xhi, g_xhi);
    cudaGetSymbolAddress((void**)&whi, g_whi);
    cudaGetSymbolAddress((void**)&wlo, g_wlo);
    cudaGetSymbolAddress((void**)&wohi, g_wohi);
    cudaGetSymbolAddress((void**)&ohi, g_ohi);

    // fused prep: weight splits + x transpose/convert (one launch)
    prep_k<<<5120, 256>>>(w_qkv, w_out, x);
    // QKV projection (2-pass, W corrected): grid = (hw 8, o 12, slabs 64)
    mma_gemm<0, 2><<<dim3(8, 12, 64), 128, SMEM_TOTAL>>>(xhi, whi, wlo, b_qkv, nullptr);
    // attention: grid = (hw tiles 64, b*heads 32), 256 threads
    attn_k<<<dim3(64, 32), 256, ATTN_SMEM>>>(rel_pos);
    // output projection (single fp16 pass): grid = (8, 4, 64)
    mma_gemm<1, 1><<<dim3(8, 4, 64), 128, SMEM_TOTAL>>>(ohi, wohi, nullptr, b_out, y);
}

// round 14
// speedup vs baseline: 1.1779x; 1.1779x over previous
#include <cuda_runtime.h>
#include <cuda_fp16.h>
#include <cstdint>

// ---------------- problem constants ----------------
constexpr int B_    = 4;
constexpr int T_    = 16;
constexpr int HEADS = 8;
constexpr int HW    = 1024;       // 32*32
constexpr int NSLAB = B_ * T_;    // 64
constexpr float QSCALE = 0.17677669529663687f;

// ---------------- scratch (__device__ globals) ----------------
__device__ __half g_xhi[NSLAB * HW * 256];  // [slab][hw][c]
__device__ __half g_whi[768 * 256];         // [o][c]
__device__ __half g_wlo[768 * 256];
__device__ __half g_wohi[256 * 256];
__device__ __half g_q[B_ * HEADS * T_ * 32 * HW];  // fp16 [b][head][t][d][hw]
__device__ __half g_k[B_ * HEADS * T_ * 32 * HW];
__device__ __half g_v[B_ * HEADS * T_ * 32 * HW];
__device__ __half g_ohi[NSLAB * HW * 256];  // [slab][hw][e]

// ---------------- PTX helpers ----------------
__device__ __forceinline__ uint32_t smem_u32(const void* p) {
    uint32_t a;
    asm("{ .reg .u64 t; cvta.to.shared.u64 t, %1; cvt.u32.u64 %0, t; }" : "=r"(a) : "l"(p));
    return a;
}
__device__ __forceinline__ void cp16(uint32_t s, const void* g) {
    asm volatile("cp.async.cg.shared.global [%0], [%1], 16;" :: "r"(s), "l"(g) : "memory");
}
__device__ __forceinline__ void cp_commit() {
    asm volatile("cp.async.commit_group;" ::: "memory");
}
template <int N>
__device__ __forceinline__ void cp_wait() {
    asm volatile("cp.async.wait_group %0;" :: "n"(N) : "memory");
}
__device__ __forceinline__ void ldsm4(uint32_t& r0, uint32_t& r1, uint32_t& r2,
                                      uint32_t& r3, uint32_t a) {
    asm volatile("ldmatrix.sync.aligned.m8n8.x4.shared.b16 {%0,%1,%2,%3}, [%4];"
                 : "=r"(r0), "=r"(r1), "=r"(r2), "=r"(r3) : "r"(a));
}
__device__ __forceinline__ void mma16816(float& c0, float& c1, float& c2, float& c3,
                                         uint32_t a0, uint32_t a1, uint32_t a2,
                                         uint32_t a3, uint32_t b0, uint32_t b1) {
    asm volatile(
        "mma.sync.aligned.m16n8k16.row.col.f32.f16.f16.f32 "
        "{%0,%1,%2,%3}, {%4,%5,%6,%7}, {%8,%9}, {%0,%1,%2,%3};"
        : "+f"(c0), "+f"(c1), "+f"(c2), "+f"(c3)
        : "r"(a0), "r"(a1), "r"(a2), "r"(a3), "r"(b0), "r"(b1));
}

// ---------------- SMEM staging layout (swizzled, no padding) ----------------
constexpr int O_AHI = 0;
constexpr int O_BHI = 8192;
constexpr int O_BLO = 12288;
constexpr int STAGE = 16384;
constexpr int SMEM_TOTAL = 49152;           // 2 stages + epilogue headroom
constexpr int CSTR = 132;                   // C smem row stride (floats)

__device__ __forceinline__ uint32_t swz(int row, int chunk) {
    return (uint32_t)(row * 64 + ((chunk ^ ((row >> 1) & 3)) << 4));
}

// ================= tensor-core GEMM =================
// D[hw 128, o 64] = A[hw, K] * B[o, K]^T, K=256.
// PASSES==2: A_hi*(B_hi + B_lo). PASSES==1: plain fp16.
// EPI 0: q/k/v fp16 epilogue. EPI 1: +bias -> f32 Y.
// 128 threads, 4 warps (2m x 2n), warp tile 64x32, 2-stage cp.async, 4 CTAs/SM.
template <int EPI, int PASSES>
__global__ __launch_bounds__(128, 4) void mma_gemm(const __half* __restrict__ Ahig,
                                                   const __half* __restrict__ Bhig,
                                                   const __half* __restrict__ Blog,
                                                   const float* __restrict__ bias,
                                                   float* __restrict__ Y) {
    extern __shared__ __align__(1024) char smem[];
    const uint32_t sb = smem_u32(smem);
    const int tid  = threadIdx.x;
    const int wid  = tid >> 5;
    const int lane = tid & 31;
    const int wm = wid & 1;     // warp m tile (64 rows)
    const int wn = wid >> 1;    // warp n tile (32 cols)

    const int slab = blockIdx.z;
    const int hw0  = blockIdx.x * 128;
    const int n0   = blockIdx.y * 64;

    const __half* ah = Ahig + ((size_t)slab * HW + hw0) * 256;
    const __half* bh = Bhig + (size_t)n0 * 256;
    const __half* bl = (PASSES == 2) ? Blog + (size_t)n0 * 256 : bh;

    const int rowA0 = wm * 64 + (lane & 15);
    const int chA   = lane >> 4;
    const int rowB  = wn * 32 + lane;
    const uint32_t adrA[4] = {
        sb + O_AHI + swz(rowA0,      chA),
        sb + O_AHI + swz(rowA0 + 16, chA),
        sb + O_AHI + swz(rowA0 + 32, chA),
        sb + O_AHI + swz(rowA0 + 48, chA)};
    const uint32_t adrB = sb + O_BHI + swz(rowB, 0);

    float acc[4][4][4];
#pragma unroll
    for (int mt = 0; mt < 4; mt++)
#pragma unroll
        for (int nt = 0; nt < 4; nt++)
#pragma unroll
            for (int r = 0; r < 4; r++) acc[mt][nt][r] = 0.0f;

    const int rA = tid >> 2, sA = tid & 3;
    const int rswIO = (rA >> 1) & 3;
    const uint32_t soIO = (uint32_t)(rA * 64 + ((sA ^ rswIO) << 4));

    auto issue = [&](int kt, int s) {
        const uint32_t base = sb + s * STAGE;
        const int kbase = kt * 32;
#pragma unroll
        for (int v = 0; v < 4; v++) {
            const uint32_t so = soIO + (uint32_t)(v * 2048);
            const size_t go = (size_t)(rA + 32 * v) * 256 + kbase + sA * 8;
            cp16(base + O_AHI + so, ah + go);
        }
#pragma unroll
        for (int v = 0; v < 2; v++) {
            const uint32_t so = soIO + (uint32_t)(v * 2048);
            const size_t go = (size_t)(rA + 32 * v) * 256 + kbase + sA * 8;
            cp16(base + O_BHI + so, bh + go);
            if (PASSES == 2) cp16(base + O_BLO + so, bl + go);
        }
    };

    issue(0, 0);
    cp_commit();

    uint32_t so = 0;
    for (int kt = 0; kt < 8; kt++) {
        if (kt < 7) {
            issue(kt + 1, (kt + 1) & 1);
            cp_commit();
            cp_wait<1>();
        } else {
            cp_wait<0>();
        }
        __syncthreads();

#pragma unroll
        for (int kk = 0; kk < 2; kk++) {
            const uint32_t kx = (uint32_t)(kk << 5);
            uint32_t ahi[4][4];
            uint32_t b0h[4], b1h[4];
#pragma unroll
            for (int mt = 0; mt < 4; mt++)
                ldsm4(ahi[mt][0], ahi[mt][1], ahi[mt][2], ahi[mt][3],
                      (adrA[mt] ^ kx) + so);
            const uint32_t bb = (adrB ^ kx) + so;
            ldsm4(b0h[0], b0h[1], b0h[2], b0h[3], bb);
            ldsm4(b1h[0], b1h[1], b1h[2], b1h[3], bb ^ 0x10);

            if (PASSES == 2) {
                uint32_t b0l[4], b1l[4];
                ldsm4(b0l[0], b0l[1], b0l[2], b0l[3], bb + 4096);
                ldsm4(b1l[0], b1l[1], b1l[2], b1l[3], (bb ^ 0x10) + 4096);
#pragma unroll
                for (int mt = 0; mt < 4; mt++)
#pragma unroll
                    for (int nt = 0; nt < 4; nt++)
                        mma16816(acc[mt][nt][0], acc[mt][nt][1], acc[mt][nt][2],
                                 acc[mt][nt][3], ahi[mt][0], ahi[mt][1],
                                 ahi[mt][2], ahi[mt][3], b0h[nt], b1h[nt]);
#pragma unroll
                for (int mt = 0; mt < 4; mt++)
#pragma unroll
                    for (int nt = 0; nt < 4; nt++)
                        mma16816(acc[mt][nt][0], acc[mt][nt][1], acc[mt][nt][2],
                                 acc[mt][nt][3], ahi[mt][0], ahi[mt][1],
                                 ahi[mt][2], ahi[mt][3], b0l[nt], b1l[nt]);
            } else {
#pragma unroll
                for (int mt = 0; mt < 4; mt++)
#pragma unroll
                    for (int nt = 0; nt < 4; nt++)
                        mma16816(acc[mt][nt][0], acc[mt][nt][1], acc[mt][nt][2],
                                 acc[mt][nt][3], ahi[mt][0], ahi[mt][1],
                                 ahi[mt][2], ahi[mt][3], b0h[nt], b1h[nt]);
            }
        }
        __syncthreads();
        so ^= (uint32_t)STAGE;
    }

    // ---------------- epilogue: transpose through SMEM ----------------
    float* cs = (float*)smem;   // [64 n][CSTR m]
#pragma unroll
    for (int mt = 0; mt < 4; mt++)
#pragma unroll
        for (int nt = 0; nt < 4; nt++) {
            const int n = wn * 32 + nt * 8 + (lane & 3) * 2;
            const int m = wm * 64 + mt * 16 + (lane >> 2);
            cs[n * CSTR + m]           = acc[mt][nt][0];
            cs[(n + 1) * CSTR + m]     = acc[mt][nt][1];
            cs[n * CSTR + m + 8]       = acc[mt][nt][2];
            cs[(n + 1) * CSTR + m + 8] = acc[mt][nt][3];
        }
    __syncthreads();

    const int b_ = slab >> 4, t_ = slab & 15;
#pragma unroll
    for (int r = 0; r < 16; r++) {
        const int n = wid * 16 + r;
        const int o = n0 + n;
        float4 v = *(const float4*)&cs[n * CSTR + lane * 4];
        const float bv = bias[o];
        if (EPI == 0) {
            const int which = o >> 8;
            const int head  = (o >> 5) & 7;
            const int d     = o & 31;
            __half* dst = (which == 0) ? g_q : (which == 1 ? g_k : g_v);
            const float sc = (which == 0) ? QSCALE : 1.0f;
            const __half2 h01 = __halves2half2(__float2half_rn((v.x + bv) * sc),
                                               __float2half_rn((v.y + bv) * sc));
            const __half2 h23 = __halves2half2(__float2half_rn((v.z + bv) * sc),
                                               __float2half_rn((v.w + bv) * sc));
            const size_t off =
                ((size_t)(((b_ * 8 + head) * 16 + t_) * 32 + d)) * 1024 + hw0 + lane * 4;
            uint2 pk;
            pk.x = *(const uint32_t*)&h01;
            pk.y = *(const uint32_t*)&h23;
            *(uint2*)(dst + off) = pk;
        } else {
            v.x += bv; v.y += bv; v.z += bv; v.w += bv;
            *(float4*)(Y + ((size_t)slab * 256 + o) * 1024 + hw0 + lane * 4) = v;
        }
    }
}

// ================= fused prep kernel =================
// blocks [0,768):    w_qkv hi/lo split (row = bid, 256 elems)
// blocks [768,1024): w_out fp16 convert
// blocks [1024,5120): x [slab][c][hw] -> g_xhi [slab][hw][c] fp16 (64x64 tiles)
__global__ __launch_bounds__(256) void prep_k(const float* __restrict__ w_qkv,
                                              const float* __restrict__ w_out,
                                              const float* __restrict__ x) {
    const int bid = blockIdx.x;
    const int tid = threadIdx.x;

    if (bid < 768) {
        const int i = bid * 256 + tid;
        const float f = w_qkv[i];
        const __half h = __float2half_rn(f);
        g_whi[i] = h;
        g_wlo[i] = __float2half_rn(f - __half2float(h));
        return;
    }
    if (bid < 1024) {
        const int i = (bid - 768) * 256 + tid;
        g_wohi[i] = __float2half_rn(w_out[i]);
        return;
    }

    __shared__ float ts[64][65];
    const int id = bid - 1024;
    const int h0 = (id & 15) * 64;
    const int c0 = ((id >> 4) & 3) * 64;
    const int slab = id >> 6;
    const int r = tid >> 2;
    const int q4 = tid & 3;

    const float* src = x + ((size_t)slab * 256 + c0 + r) * 1024 + h0 + q4 * 16;
#pragma unroll
    for (int j = 0; j < 4; j++) {
        const float4 v = *(const float4*)(src + j * 4);
        ts[r][q4 * 16 + j * 4 + 0] = v.x;
        ts[r][q4 * 16 + j * 4 + 1] = v.y;
        ts[r][q4 * 16 + j * 4 + 2] = v.z;
        ts[r][q4 * 16 + j * 4 + 3] = v.w;
    }
    __syncthreads();

    __half hb[16];
#pragma unroll
    for (int j = 0; j < 16; j++)
        hb[j] = __float2half_rn(ts[q4 * 16 + j][r]);
    const size_t o = ((size_t)slab * 1024 + h0 + r) * 256 + c0 + q4 * 16;
    *(uint4*)(g_xhi + o)     = ((uint4*)hb)[0];
    *(uint4*)(g_xhi + o + 8) = ((uint4*)hb)[1];
}

// ================= attention (T=16), fp16 in, fp16 out =================
__device__ __forceinline__ unsigned long long pack2(float lo, float hi) {
    unsigned long long r;
    asm("mov.b64 %0, {%1, %2};" : "=l"(r) : "f"(lo), "f"(hi));
    return r;
}
__device__ __forceinline__ void unpack2(unsigned long long p, float& lo, float& hi) {
    asm("mov.b64 {%0, %1}, %2;" : "=f"(lo), "=f"(hi) : "l"(p));
}
__device__ __forceinline__ unsigned long long ffma2(unsigned long long a,
                                                    unsigned long long b,
                                                    unsigned long long c) {
    unsigned long long d;
    asm("fma.rn.f32x2 %0, %1, %2, %3;" : "=l"(d) : "l"(a), "l"(b), "l"(c));
    return d;
}

constexpr int KVP = 516;
constexpr int ATTN_SMEM = 2 * 16 * KVP * 4;   // 66048 bytes

__global__ __launch_bounds__(256) void attn_k(const float* __restrict__ rel_pos) {
    extern __shared__ __align__(16) float asmem[];
    float* k_s = asmem;                 // [16][KVP]
    float* v_s = asmem + 16 * KVP;

    const int bh  = blockIdx.y;            // b*8 + head
    const int hw0 = blockIdx.x * 16;
    const int tid = threadIdx.x;
    const int hwl = tid & 15;
    const int i   = tid >> 4;              // query t 0..15

    const size_t ubase = (size_t)bh * 512 * HW;

#pragma unroll
    for (int it = 0; it < 4; it++) {
        const int slot = tid + 256 * it;   // 0..1023
        const int td  = slot >> 1;
        const int seg = (slot & 1) * 8;
        const size_t go = ubase + (size_t)td * HW + hw0 + seg;
        const uint4 rk = *(const uint4*)(g_k + go);
        const uint4 rv = *(const uint4*)(g_v + go);
        const __half2* hk = (const __half2*)&rk;
        const __half2* hv = (const __half2*)&rv;
#pragma unroll
        for (int c = 0; c < 4; c++) {
            const float2 fk = __half22float2(hk[c]);
            const float2 fv = __half22float2(hv[c]);
            k_s[(seg + 2 * c)     * KVP + td] = fk.x;
            k_s[(seg + 2 * c + 1) * KVP + td] = fk.y;
            v_s[(seg + 2 * c)     * KVP + td] = fv.x;
            v_s[(seg + 2 * c + 1) * KVP + td] = fv.y;
        }
    }
    __syncthreads();

    unsigned long long qp[16];
    const size_t qbase = ubase + (size_t)i * 32 * HW + hw0 + hwl;
#pragma unroll
    for (int c = 0; c < 16; c++)
        qp[c] = pack2(__half2float(g_q[qbase + (size_t)(2 * c) * HW]),
                      __half2float(g_q[qbase + (size_t)(2 * c + 1) * HW]));

    const int head = bh & 7;
    const float* rp = rel_pos + head * 256 + i * 16;

    float s[16];
#pragma unroll
    for (int j = 0; j < 16; j++) {
        const ulonglong2* kp = (const ulonglong2*)&k_s[hwl * KVP + j * 32];
        unsigned long long acc = 0ull;
#pragma unroll
        for (int c = 0; c < 8; c++) {
            const ulonglong2 kk = kp[c];
            acc = ffma2(qp[2 * c],     kk.x, acc);
            acc = ffma2(qp[2 * c + 1], kk.y, acc);
        }
        float lo, hi;
        unpack2(acc, lo, hi);
        s[j] = lo + hi + rp[j];
    }

    float mx = s[0];
#pragma unroll
    for (int j = 1; j < 16; j++) mx = fmaxf(mx, s[j]);
    float sum = 0.0f;
#pragma unroll
    for (int j = 0; j < 16; j++) { s[j] = expf(s[j] - mx); sum += s[j]; }
    const float inv = 1.0f / sum;

    unsigned long long o2[16];
#pragma unroll
    for (int c = 0; c < 16; c++) o2[c] = 0ull;
#pragma unroll
    for (int j = 0; j < 16; j++) {
        const unsigned long long pp = pack2(s[j], s[j]);
        const ulonglong2* vp = (const ulonglong2*)&v_s[hwl * KVP + j * 32];
#pragma unroll
        for (int c = 0; c < 8; c++) {
            const ulonglong2 vv = vp[c];
            o2[2 * c]     = ffma2(pp, vv.x, o2[2 * c]);
            o2[2 * c + 1] = ffma2(pp, vv.y, o2[2 * c + 1]);
        }
    }

    const int b_ = bh >> 3;
    const size_t obase =
        ((size_t)((b_ * 16 + i)) * 1024 + hw0 + hwl) * 256 + head * 32;
#pragma unroll
    for (int c = 0; c < 16; c++) {
        float lo, hi;
        unpack2(o2[c], lo, hi);
        ((__half2*)(g_ohi + obase))[c] =
            __halves2half2(__float2half_rn(lo * inv), __float2half_rn(hi * inv));
    }
}

// ================= host =================
extern "C" void kernel_launch(void* const* d_in, const int* in_sizes, int n_in,
                              void* d_out, int out_size) {
    const float* x       = (const float*)d_in[0];
    const float* rel_pos = (const float*)d_in[1];
    const float* w_qkv   = (const float*)d_in[2];
    const float* b_qkv   = (const float*)d_in[3];
    const float* w_out   = (const float*)d_in[4];
    const float* b_out   = (const float*)d_in[5];
    float* y = (float*)d_out;

    cudaFuncSetAttribute(mma_gemm<0, 2>, cudaFuncAttributeMaxDynamicSharedMemorySize, SMEM_TOTAL);
    cudaFuncSetAttribute(mma_gemm<1, 1>, cudaFuncAttributeMaxDynamicSharedMemorySize, SMEM_TOTAL);
    cudaFuncSetAttribute(attn_k, cudaFuncAttributeMaxDynamicSharedMemorySize, ATTN_SMEM);

    __half *xhi, *whi, *wlo, *wohi, *ohi;
    cudaGetSymbolAddress((void**)&xhi, g_xhi);
    cudaGetSymbolAddress((void**)&whi, g_whi);
    cudaGetSymbolAddress((void**)&wlo, g_wlo);
    cudaGetSymbolAddress((void**)&wohi, g_wohi);
    cudaGetSymbolAddress((void**)&ohi, g_ohi);

    // fused prep: weight splits + x transpose/convert (one launch)
    prep_k<<<5120, 256>>>(w_qkv, w_out, x);
    // QKV projection (2-pass, W corrected): grid = (hw 8, o 12, slabs 64)
    mma_gemm<0, 2><<<dim3(8, 12, 64), 128, SMEM_TOTAL>>>(xhi, whi, wlo, b_qkv, nullptr);
    // attention: grid = (hw tiles 64, b*heads 32), 256 threads
    attn_k<<<dim3(64, 32), 256, ATTN_SMEM>>>(rel_pos);
    // output projection (single fp16 pass): grid = (8, 4, 64)
    mma_gemm<1, 1><<<dim3(8, 4, 64), 128, SMEM_TOTAL>>>(ohi, wohi, nullptr, b_out, y);
}

// round 15
// speedup vs baseline: 1.4297x; 1.2137x over previous
#include <cuda_runtime.h>
#include <cuda_fp16.h>
#include <cstdint>

// ---------------- problem constants ----------------
constexpr int B_    = 4;
constexpr int T_    = 16;
constexpr int HEADS = 8;
constexpr int HW    = 1024;       // 32*32
constexpr int NSLAB = B_ * T_;    // 64
constexpr float QSCALE = 0.17677669529663687f;

// ---------------- scratch (__device__ globals) ----------------
__device__ __half g_xhi[NSLAB * HW * 256];  // [slab][hw][c]
__device__ __half g_whi[768 * 256];         // [o][c]
__device__ __half g_wohi[256 * 256];
__device__ __half g_q[B_ * HEADS * T_ * 32 * HW];  // fp16 [b][head][t][d][hw]
__device__ __half g_k[B_ * HEADS * T_ * 32 * HW];
__device__ __half g_v[B_ * HEADS * T_ * 32 * HW];
__device__ __half g_ohi[NSLAB * HW * 256];  // [slab][hw][e]

// ---------------- PTX helpers ----------------
__device__ __forceinline__ uint32_t smem_u32(const void* p) {
    uint32_t a;
    asm("{ .reg .u64 t; cvta.to.shared.u64 t, %1; cvt.u32.u64 %0, t; }" : "=r"(a) : "l"(p));
    return a;
}
__device__ __forceinline__ void cp16(uint32_t s, const void* g) {
    asm volatile("cp.async.cg.shared.global [%0], [%1], 16;" :: "r"(s), "l"(g) : "memory");
}
__device__ __forceinline__ void cp_commit() {
    asm volatile("cp.async.commit_group;" ::: "memory");
}
template <int N>
__device__ __forceinline__ void cp_wait() {
    asm volatile("cp.async.wait_group %0;" :: "n"(N) : "memory");
}
__device__ __forceinline__ void ldsm4(uint32_t& r0, uint32_t& r1, uint32_t& r2,
                                      uint32_t& r3, uint32_t a) {
    asm volatile("ldmatrix.sync.aligned.m8n8.x4.shared.b16 {%0,%1,%2,%3}, [%4];"
                 : "=r"(r0), "=r"(r1), "=r"(r2), "=r"(r3) : "r"(a));
}
__device__ __forceinline__ void mma16816(float& c0, float& c1, float& c2, float& c3,
                                         uint32_t a0, uint32_t a1, uint32_t a2,
                                         uint32_t a3, uint32_t b0, uint32_t b1) {
    asm volatile(
        "mma.sync.aligned.m16n8k16.row.col.f32.f16.f16.f32 "
        "{%0,%1,%2,%3}, {%4,%5,%6,%7}, {%8,%9}, {%0,%1,%2,%3};"
        : "+f"(c0), "+f"(c1), "+f"(c2), "+f"(c3)
        : "r"(a0), "r"(a1), "r"(a2), "r"(a3), "r"(b0), "r"(b1));
}

// ---------------- SMEM staging layout (swizzled, no padding) ----------------
constexpr int O_AHI = 0;
constexpr int O_BHI = 8192;
constexpr int O_BLO = 12288;
constexpr int STAGE = 16384;
constexpr int SMEM_TOTAL = 49152;           // 2 stages + epilogue headroom
constexpr int CSTR = 132;                   // C smem row stride (floats)

__device__ __forceinline__ uint32_t swz(int row, int chunk) {
    return (uint32_t)(row * 64 + ((chunk ^ ((row >> 1) & 3)) << 4));
}

// ================= tensor-core GEMM =================
// D[hw 128, o 64] = A[hw, K] * B[o, K]^T, K=256.
// PASSES==2: A_hi*(B_hi + B_lo). PASSES==1: plain fp16.
// EPI 0: q/k/v fp16 epilogue. EPI 1: +bias -> f32 Y.
// 128 threads, 4 warps (2m x 2n), warp tile 64x32, 2-stage cp.async, 4 CTAs/SM.
template <int EPI, int PASSES>
__global__ __launch_bounds__(128, 4) void mma_gemm(const __half* __restrict__ Ahig,
                                                   const __half* __restrict__ Bhig,
                                                   const __half* __restrict__ Blog,
                                                   const float* __restrict__ bias,
                                                   float* __restrict__ Y) {
    extern __shared__ __align__(1024) char smem[];
    const uint32_t sb = smem_u32(smem);
    const int tid  = threadIdx.x;
    const int wid  = tid >> 5;
    const int lane = tid & 31;
    const int wm = wid & 1;     // warp m tile (64 rows)
    const int wn = wid >> 1;    // warp n tile (32 cols)

    const int slab = blockIdx.z;
    const int hw0  = blockIdx.x * 128;
    const int n0   = blockIdx.y * 64;

    const __half* ah = Ahig + ((size_t)slab * HW + hw0) * 256;
    const __half* bh = Bhig + (size_t)n0 * 256;
    const __half* bl = (PASSES == 2) ? Blog + (size_t)n0 * 256 : bh;

    const int rowA0 = wm * 64 + (lane & 15);
    const int chA   = lane >> 4;
    const int rowB  = wn * 32 + lane;
    const uint32_t adrA[4] = {
        sb + O_AHI + swz(rowA0,      chA),
        sb + O_AHI + swz(rowA0 + 16, chA),
        sb + O_AHI + swz(rowA0 + 32, chA),
        sb + O_AHI + swz(rowA0 + 48, chA)};
    const uint32_t adrB = sb + O_BHI + swz(rowB, 0);

    float acc[4][4][4];
#pragma unroll
    for (int mt = 0; mt < 4; mt++)
#pragma unroll
        for (int nt = 0; nt < 4; nt++)
#pragma unroll
            for (int r = 0; r < 4; r++) acc[mt][nt][r] = 0.0f;

    const int rA = tid >> 2, sA = tid & 3;
    const int rswIO = (rA >> 1) & 3;
    const uint32_t soIO = (uint32_t)(rA * 64 + ((sA ^ rswIO) << 4));

    auto issue = [&](int kt, int s) {
        const uint32_t base = sb + s * STAGE;
        const int kbase = kt * 32;
#pragma unroll
        for (int v = 0; v < 4; v++) {
            const uint32_t so = soIO + (uint32_t)(v * 2048);
            const size_t go = (size_t)(rA + 32 * v) * 256 + kbase + sA * 8;
            cp16(base + O_AHI + so, ah + go);
        }
#pragma unroll
        for (int v = 0; v < 2; v++) {
            const uint32_t so = soIO + (uint32_t)(v * 2048);
            const size_t go = (size_t)(rA + 32 * v) * 256 + kbase + sA * 8;
            cp16(base + O_BHI + so, bh + go);
            if (PASSES == 2) cp16(base + O_BLO + so, bl + go);
        }
    };

    issue(0, 0);
    cp_commit();

    uint32_t so = 0;
    for (int kt = 0; kt < 8; kt++) {
        if (kt < 7) {
            issue(kt + 1, (kt + 1) & 1);
            cp_commit();
            cp_wait<1>();
        } else {
            cp_wait<0>();
        }
        __syncthreads();

#pragma unroll
        for (int kk = 0; kk < 2; kk++) {
            const uint32_t kx = (uint32_t)(kk << 5);
            uint32_t ahi[4][4];
            uint32_t b0h[4], b1h[4];
#pragma unroll
            for (int mt = 0; mt < 4; mt++)
                ldsm4(ahi[mt][0], ahi[mt][1], ahi[mt][2], ahi[mt][3],
                      (adrA[mt] ^ kx) + so);
            const uint32_t bb = (adrB ^ kx) + so;
            ldsm4(b0h[0], b0h[1], b0h[2], b0h[3], bb);
            ldsm4(b1h[0], b1h[1], b1h[2], b1h[3], bb ^ 0x10);

            if (PASSES == 2) {
                uint32_t b0l[4], b1l[4];
                ldsm4(b0l[0], b0l[1], b0l[2], b0l[3], bb + 4096);
                ldsm4(b1l[0], b1l[1], b1l[2], b1l[3], (bb ^ 0x10) + 4096);
#pragma unroll
                for (int mt = 0; mt < 4; mt++)
#pragma unroll
                    for (int nt = 0; nt < 4; nt++)
                        mma16816(acc[mt][nt][0], acc[mt][nt][1], acc[mt][nt][2],
                                 acc[mt][nt][3], ahi[mt][0], ahi[mt][1],
                                 ahi[mt][2], ahi[mt][3], b0h[nt], b1h[nt]);
#pragma unroll
                for (int mt = 0; mt < 4; mt++)
#pragma unroll
                    for (int nt = 0; nt < 4; nt++)
                        mma16816(acc[mt][nt][0], acc[mt][nt][1], acc[mt][nt][2],
                                 acc[mt][nt][3], ahi[mt][0], ahi[mt][1],
                                 ahi[mt][2], ahi[mt][3], b0l[nt], b1l[nt]);
            } else {
#pragma unroll
                for (int mt = 0; mt < 4; mt++)
#pragma unroll
                    for (int nt = 0; nt < 4; nt++)
                        mma16816(acc[mt][nt][0], acc[mt][nt][1], acc[mt][nt][2],
                                 acc[mt][nt][3], ahi[mt][0], ahi[mt][1],
                                 ahi[mt][2], ahi[mt][3], b0h[nt], b1h[nt]);
            }
        }
        __syncthreads();
        so ^= (uint32_t)STAGE;
    }

    // ---------------- epilogue: transpose through SMEM ----------------
    float* cs = (float*)smem;   // [64 n][CSTR m]
#pragma unroll
    for (int mt = 0; mt < 4; mt++)
#pragma unroll
        for (int nt = 0; nt < 4; nt++) {
            const int n = wn * 32 + nt * 8 + (lane & 3) * 2;
            const int m = wm * 64 + mt * 16 + (lane >> 2);
            cs[n * CSTR + m]           = acc[mt][nt][0];
            cs[(n + 1) * CSTR + m]     = acc[mt][nt][1];
            cs[n * CSTR + m + 8]       = acc[mt][nt][2];
            cs[(n + 1) * CSTR + m + 8] = acc[mt][nt][3];
        }
    __syncthreads();

    const int b_ = slab >> 4, t_ = slab & 15;
#pragma unroll
    for (int r = 0; r < 16; r++) {
        const int n = wid * 16 + r;
        const int o = n0 + n;
        float4 v = *(const float4*)&cs[n * CSTR + lane * 4];
        const float bv = bias[o];
        if (EPI == 0) {
            const int which = o >> 8;
            const int head  = (o >> 5) & 7;
            const int d     = o & 31;
            __half* dst = (which == 0) ? g_q : (which == 1 ? g_k : g_v);
            const float sc = (which == 0) ? QSCALE : 1.0f;
            const __half2 h01 = __halves2half2(__float2half_rn((v.x + bv) * sc),
                                               __float2half_rn((v.y + bv) * sc));
            const __half2 h23 = __halves2half2(__float2half_rn((v.z + bv) * sc),
                                               __float2half_rn((v.w + bv) * sc));
            const size_t off =
                ((size_t)(((b_ * 8 + head) * 16 + t_) * 32 + d)) * 1024 + hw0 + lane * 4;
            uint2 pk;
            pk.x = *(const uint32_t*)&h01;
            pk.y = *(const uint32_t*)&h23;
            *(uint2*)(dst + off) = pk;
        } else {
            v.x += bv; v.y += bv; v.z += bv; v.w += bv;
            *(float4*)(Y + ((size_t)slab * 256 + o) * 1024 + hw0 + lane * 4) = v;
        }
    }
}

// ================= fused prep kernel =================
// blocks [0,768):    w_qkv fp16 convert (row = bid, 256 elems)
// blocks [768,1024): w_out fp16 convert
// blocks [1024,5120): x [slab][c][hw] -> g_xhi [slab][hw][c] fp16 (64x64 tiles)
__global__ __launch_bounds__(256) void prep_k(const float* __restrict__ w_qkv,
                                              const float* __restrict__ w_out,
                                              const float* __restrict__ x) {
    const int bid = blockIdx.x;
    const int tid = threadIdx.x;

    if (bid < 768) {
        const int i = bid * 256 + tid;
        g_whi[i] = __float2half_rn(w_qkv[i]);
        return;
    }
    if (bid < 1024) {
        const int i = (bid - 768) * 256 + tid;
        g_wohi[i] = __float2half_rn(w_out[i]);
        return;
    }

    __shared__ float ts[64][65];
    const int id = bid - 1024;
    const int h0 = (id & 15) * 64;
    const int c0 = ((id >> 4) & 3) * 64;
    const int slab = id >> 6;
    const int r = tid >> 2;
    const int q4 = tid & 3;

    const float* src = x + ((size_t)slab * 256 + c0 + r) * 1024 + h0 + q4 * 16;
#pragma unroll
    for (int j = 0; j < 4; j++) {
        const float4 v = *(const float4*)(src + j * 4);
        ts[r][q4 * 16 + j * 4 + 0] = v.x;
        ts[r][q4 * 16 + j * 4 + 1] = v.y;
        ts[r][q4 * 16 + j * 4 + 2] = v.z;
        ts[r][q4 * 16 + j * 4 + 3] = v.w;
    }
    __syncthreads();

    __half hb[16];
#pragma unroll
    for (int j = 0; j < 16; j++)
        hb[j] = __float2half_rn(ts[q4 * 16 + j][r]);
    const size_t o = ((size_t)slab * 1024 + h0 + r) * 256 + c0 + q4 * 16;
    *(uint4*)(g_xhi + o)     = ((uint4*)hb)[0];
    *(uint4*)(g_xhi + o + 8) = ((uint4*)hb)[1];
}

// ================= attention (T=16), fp16 in, fp16 out =================
__device__ __forceinline__ unsigned long long pack2(float lo, float hi) {
    unsigned long long r;
    asm("mov.b64 %0, {%1, %2};" : "=l"(r) : "f"(lo), "f"(hi));
    return r;
}
__device__ __forceinline__ void unpack2(unsigned long long p, float& lo, float& hi) {
    asm("mov.b64 {%0, %1}, %2;" : "=f"(lo), "=f"(hi) : "l"(p));
}
__device__ __forceinline__ unsigned long long ffma2(unsigned long long a,
                                                    unsigned long long b,
                                                    unsigned long long c) {
    unsigned long long d;
    asm("fma.rn.f32x2 %0, %1, %2, %3;" : "=l"(d) : "l"(a), "l"(b), "l"(c));
    return d;
}

constexpr int KVP = 516;
constexpr int ATTN_SMEM = 2 * 16 * KVP * 4;   // 66048 bytes

__global__ __launch_bounds__(256) void attn_k(const float* __restrict__ rel_pos) {
    extern __shared__ __align__(16) float asmem[];
    float* k_s = asmem;                 // [16][KVP]
    float* v_s = asmem + 16 * KVP;

    const int bh  = blockIdx.y;            // b*8 + head
    const int hw0 = blockIdx.x * 16;
    const int tid = threadIdx.x;
    const int hwl = tid & 15;
    const int i   = tid >> 4;              // query t 0..15

    const size_t ubase = (size_t)bh * 512 * HW;

#pragma unroll
    for (int it = 0; it < 4; it++) {
        const int slot = tid + 256 * it;   // 0..1023
        const int td  = slot >> 1;
        const int seg = (slot & 1) * 8;
        const size_t go = ubase + (size_t)td * HW + hw0 + seg;
        const uint4 rk = *(const uint4*)(g_k + go);
        const uint4 rv = *(const uint4*)(g_v + go);
        const __half2* hk = (const __half2*)&rk;
        const __half2* hv = (const __half2*)&rv;
#pragma unroll
        for (int c = 0; c < 4; c++) {
            const float2 fk = __half22float2(hk[c]);
            const float2 fv = __half22float2(hv[c]);
            k_s[(seg + 2 * c)     * KVP + td] = fk.x;
            k_s[(seg + 2 * c + 1) * KVP + td] = fk.y;
            v_s[(seg + 2 * c)     * KVP + td] = fv.x;
            v_s[(seg + 2 * c + 1) * KVP + td] = fv.y;
        }
    }
    __syncthreads();

    unsigned long long qp[16];
    const size_t qbase = ubase + (size_t)i * 32 * HW + hw0 + hwl;
#pragma unroll
    for (int c = 0; c < 16; c++)
        qp[c] = pack2(__half2float(g_q[qbase + (size_t)(2 * c) * HW]),
                      __half2float(g_q[qbase + (size_t)(2 * c + 1) * HW]));

    const int head = bh & 7;
    const float* rp = rel_pos + head * 256 + i * 16;

    float s[16];
#pragma unroll
    for (int j = 0; j < 16; j++) {
        const ulonglong2* kp = (const ulonglong2*)&k_s[hwl * KVP + j * 32];
        unsigned long long acc = 0ull;
#pragma unroll
        for (int c = 0; c < 8; c++) {
            const ulonglong2 kk = kp[c];
            acc = ffma2(qp[2 * c],     kk.x, acc);
            acc = ffma2(qp[2 * c + 1], kk.y, acc);
        }
        float lo, hi;
        unpack2(acc, lo, hi);
        s[j] = lo + hi + rp[j];
    }

    float mx = s[0];
#pragma unroll
    for (int j = 1; j < 16; j++) mx = fmaxf(mx, s[j]);
    float sum = 0.0f;
#pragma unroll
    for (int j = 0; j < 16; j++) { s[j] = expf(s[j] - mx); sum += s[j]; }
    const float inv = 1.0f / sum;

    unsigned long long o2[16];
#pragma unroll
    for (int c = 0; c < 16; c++) o2[c] = 0ull;
#pragma unroll
    for (int j = 0; j < 16; j++) {
        const unsigned long long pp = pack2(s[j], s[j]);
        const ulonglong2* vp = (const ulonglong2*)&v_s[hwl * KVP + j * 32];
#pragma unroll
        for (int c = 0; c < 8; c++) {
            const ulonglong2 vv = vp[c];
            o2[2 * c]     = ffma2(pp, vv.x, o2[2 * c]);
            o2[2 * c + 1] = ffma2(pp, vv.y, o2[2 * c + 1]);
        }
    }

    const int b_ = bh >> 3;
    const size_t obase =
        ((size_t)((b_ * 16 + i)) * 1024 + hw0 + hwl) * 256 + head * 32;
#pragma unroll
    for (int c = 0; c < 16; c++) {
        float lo, hi;
        unpack2(o2[c], lo, hi);
        ((__half2*)(g_ohi + obase))[c] =
            __halves2half2(__float2half_rn(lo * inv), __float2half_rn(hi * inv));
    }
}

// ================= host =================
extern "C" void kernel_launch(void* const* d_in, const int* in_sizes, int n_in,
                              void* d_out, int out_size) {
    const float* x       = (const float*)d_in[0];
    const float* rel_pos = (const float*)d_in[1];
    const float* w_qkv   = (const float*)d_in[2];
    const float* b_qkv   = (const float*)d_in[3];
    const float* w_out   = (const float*)d_in[4];
    const float* b_out   = (const float*)d_in[5];
    float* y = (float*)d_out;

    cudaFuncSetAttribute(mma_gemm<0, 1>, cudaFuncAttributeMaxDynamicSharedMemorySize, SMEM_TOTAL);
    cudaFuncSetAttribute(mma_gemm<1, 1>, cudaFuncAttributeMaxDynamicSharedMemorySize, SMEM_TOTAL);
    cudaFuncSetAttribute(attn_k, cudaFuncAttributeMaxDynamicSharedMemorySize, ATTN_SMEM);

    __half *xhi, *whi, *wohi, *ohi;
    cudaGetSymbolAddress((void**)&xhi, g_xhi);
    cudaGetSymbolAddress((void**)&whi, g_whi);
    cudaGetSymbolAddress((void**)&wohi, g_wohi);
    cudaGetSymbolAddress((void**)&ohi, g_ohi);

    // fused prep: weight converts + x transpose/convert (one launch)
    prep_k<<<5120, 256>>>(w_qkv, w_out, x);
    // QKV projection (single fp16 pass): grid = (hw 8, o 12, slabs 64)
    mma_gemm<0, 1><<<dim3(8, 12, 64), 128, SMEM_TOTAL>>>(xhi, whi, nullptr, b_qkv, nullptr);
    // attention: grid = (hw tiles 64, b*heads 32), 256 threads
    attn_k<<<dim3(64, 32), 256, ATTN_SMEM>>>(rel_pos);
    // output projection (single fp16 pass): grid = (8, 4, 64)
    mma_gemm<1, 1><<<dim3(8, 4, 64), 128, SMEM_TOTAL>>>(ohi, wohi, nullptr, b_out, y);
}

// round 16
// speedup vs baseline: 1.4539x; 1.0169x over previous
#include <cuda_runtime.h>
#include <cuda_fp16.h>
#include <cstdint>

// ---------------- problem constants ----------------
constexpr int B_    = 4;
constexpr int T_    = 16;
constexpr int HEADS = 8;
constexpr int HW    = 1024;       // 32*32
constexpr int NSLAB = B_ * T_;    // 64
constexpr float QSCALE = 0.17677669529663687f;

// ---------------- scratch (__device__ globals) ----------------
__device__ __half g_xhi[NSLAB * HW * 256];  // [slab][hw][c]
__device__ __half g_whi[768 * 256];         // [o][c]
__device__ __half g_wohi[256 * 256];
__device__ __half g_q[B_ * HEADS * T_ * 32 * HW];  // fp16 [b][head][t][d][hw]
__device__ __half g_k[B_ * HEADS * T_ * 32 * HW];
__device__ __half g_v[B_ * HEADS * T_ * 32 * HW];
__device__ __half g_ohi[NSLAB * HW * 256];  // [slab][hw][e]

// ---------------- PTX helpers ----------------
__device__ __forceinline__ uint32_t smem_u32(const void* p) {
    uint32_t a;
    asm("{ .reg .u64 t; cvta.to.shared.u64 t, %1; cvt.u32.u64 %0, t; }" : "=r"(a) : "l"(p));
    return a;
}
__device__ __forceinline__ void cp16(uint32_t s, const void* g) {
    asm volatile("cp.async.cg.shared.global [%0], [%1], 16;" :: "r"(s), "l"(g) : "memory");
}
__device__ __forceinline__ void cp_commit() {
    asm volatile("cp.async.commit_group;" ::: "memory");
}
template <int N>
__device__ __forceinline__ void cp_wait() {
    asm volatile("cp.async.wait_group %0;" :: "n"(N) : "memory");
}
__device__ __forceinline__ void ldsm4(uint32_t& r0, uint32_t& r1, uint32_t& r2,
                                      uint32_t& r3, uint32_t a) {
    asm volatile("ldmatrix.sync.aligned.m8n8.x4.shared.b16 {%0,%1,%2,%3}, [%4];"
                 : "=r"(r0), "=r"(r1), "=r"(r2), "=r"(r3) : "r"(a));
}
__device__ __forceinline__ void mma16816(float& c0, float& c1, float& c2, float& c3,
                                         uint32_t a0, uint32_t a1, uint32_t a2,
                                         uint32_t a3, uint32_t b0, uint32_t b1) {
    asm volatile(
        "mma.sync.aligned.m16n8k16.row.col.f32.f16.f16.f32 "
        "{%0,%1,%2,%3}, {%4,%5,%6,%7}, {%8,%9}, {%0,%1,%2,%3};"
        : "+f"(c0), "+f"(c1), "+f"(c2), "+f"(c3)
        : "r"(a0), "r"(a1), "r"(a2), "r"(a3), "r"(b0), "r"(b1));
}

// ---------------- SMEM staging layout (BK=64, 128B rows, SW swizzle) --------
// Row = 64 halves = 128B = 8 chunks of 16B. Chunk stored at (c ^ (row&7)).
// A: 128 rows (16KB). B: 64 rows (8KB).
constexpr int O_A   = 0;
constexpr int O_B   = 16384;
constexpr int STAGE = 24576;
constexpr int SMEM_TOTAL = 49152;           // 2 stages; epilogue cs (33.8KB) fits
constexpr int CSTR = 132;                   // C smem row stride (floats)

// ================= tensor-core GEMM =================
// D[hw 128, o 64] = A[hw, K] * B[o, K]^T, K=256, single fp16 pass.
// 128 threads, 4 warps (2m x 2n), warp tile 64x32, BK=64, 2-stage cp.async,
// 4 CTAs/SM. EPI 0: q/k/v fp16 epilogue. EPI 1: +bias -> f32 Y.
template <int EPI>
__global__ __launch_bounds__(128, 4) void mma_gemm(const __half* __restrict__ Ahig,
                                                   const __half* __restrict__ Bhig,
                                                   const float* __restrict__ bias,
                                                   float* __restrict__ Y) {
    extern __shared__ __align__(1024) char smem[];
    const uint32_t sb = smem_u32(smem);
    const int tid  = threadIdx.x;
    const int wid  = tid >> 5;
    const int lane = tid & 31;
    const int wm = wid & 1;     // warp m tile (64 rows)
    const int wn = wid >> 1;    // warp n tile (32 cols)

    const int slab = blockIdx.z;
    const int hw0  = blockIdx.x * 128;
    const int n0   = blockIdx.y * 64;

    const __half* ah = Ahig + ((size_t)slab * HW + hw0) * 256;
    const __half* bh = Bhig + (size_t)n0 * 256;

    // ldmatrix bases (kk=0, stage 0). chunk = (kk<<1)|chA, swizzled ^ (row&7);
    // carry-free composition => addr(kk) = base ^ (kk<<5); B frag2 => ^0x10.
    const int chfix = (lane >> 4) ^ (lane & 7);      // row&7 == lane&7 for A rows
    const int rowA0 = wm * 64 + (lane & 15);
    const uint32_t adrA[4] = {
        sb + O_A + (uint32_t)((rowA0)      * 128 + (chfix << 4)),
        sb + O_A + (uint32_t)((rowA0 + 16) * 128 + (chfix << 4)),
        sb + O_A + (uint32_t)((rowA0 + 32) * 128 + (chfix << 4)),
        sb + O_A + (uint32_t)((rowA0 + 48) * 128 + (chfix << 4))};
    const int rowB = wn * 32 + lane;
    const uint32_t adrB = sb + O_B + (uint32_t)(rowB * 128 + ((lane & 7) << 4));

    float acc[4][4][4];
#pragma unroll
    for (int mt = 0; mt < 4; mt++)
#pragma unroll
        for (int nt = 0; nt < 4; nt++)
#pragma unroll
            for (int r = 0; r < 4; r++) acc[mt][nt][r] = 0.0f;

    // cp.async mapping: task = tid + 128v -> row = tid>>3 + 16v, chunk = tid&7
    const int rIO = tid >> 3;                        // 0..15
    const int cIO = tid & 7;
    const uint32_t offIO =
        (uint32_t)(rIO * 128 + ((cIO ^ (rIO & 7)) << 4));
    const int gIO = cIO * 8;                         // halves within K-chunk

    auto issue = [&](int kt, int s) {
        const uint32_t base = sb + s * STAGE;
        const int kbase = kt * 64;
#pragma unroll
        for (int v = 0; v < 8; v++) {        // A rows rIO + 16v (0..127)
            cp16(base + O_A + offIO + (uint32_t)(v * 2048),
                 ah + (size_t)(rIO + 16 * v) * 256 + kbase + gIO);
        }
#pragma unroll
        for (int v = 0; v < 4; v++) {        // B rows rIO + 16v (0..63)
            cp16(base + O_B + offIO + (uint32_t)(v * 2048),
                 bh + (size_t)(rIO + 16 * v) * 256 + kbase + gIO);
        }
    };

    issue(0, 0);
    cp_commit();

    uint32_t so = 0;
    for (int kt = 0; kt < 4; kt++) {
        if (kt < 3) {
            issue(kt + 1, (kt + 1) & 1);
            cp_commit();
            cp_wait<1>();
        } else {
            cp_wait<0>();
        }
        __syncthreads();

#pragma unroll
        for (int kk = 0; kk < 4; kk++) {
            const uint32_t kx = (uint32_t)(kk << 5);
            uint32_t a[4][4];
            uint32_t b0[4], b1[4];
#pragma unroll
            for (int mt = 0; mt < 4; mt++)
                ldsm4(a[mt][0], a[mt][1], a[mt][2], a[mt][3],
                      (adrA[mt] ^ kx) + so);
            const uint32_t bb = (adrB ^ kx) + so;
            ldsm4(b0[0], b0[1], b0[2], b0[3], bb);
            ldsm4(b1[0], b1[1], b1[2], b1[3], bb ^ 0x10);
#pragma unroll
            for (int mt = 0; mt < 4; mt++)
#pragma unroll
                for (int nt = 0; nt < 4; nt++)
                    mma16816(acc[mt][nt][0], acc[mt][nt][1], acc[mt][nt][2],
                             acc[mt][nt][3], a[mt][0], a[mt][1], a[mt][2],
                             a[mt][3], b0[nt], b1[nt]);
        }
        __syncthreads();
        so ^= (uint32_t)STAGE;
    }

    // ---------------- epilogue: transpose through SMEM ----------------
    float* cs = (float*)smem;   // [64 n][CSTR m]
#pragma unroll
    for (int mt = 0; mt < 4; mt++)
#pragma unroll
        for (int nt = 0; nt < 4; nt++) {
            const int n = wn * 32 + nt * 8 + (lane & 3) * 2;
            const int m = wm * 64 + mt * 16 + (lane >> 2);
            cs[n * CSTR + m]           = acc[mt][nt][0];
            cs[(n + 1) * CSTR + m]     = acc[mt][nt][1];
            cs[n * CSTR + m + 8]       = acc[mt][nt][2];
            cs[(n + 1) * CSTR + m + 8] = acc[mt][nt][3];
        }
    __syncthreads();

    const int b_ = slab >> 4, t_ = slab & 15;
#pragma unroll
    for (int r = 0; r < 16; r++) {
        const int n = wid * 16 + r;
        const int o = n0 + n;
        float4 v = *(const float4*)&cs[n * CSTR + lane * 4];
        const float bv = bias[o];
        if (EPI == 0) {
            const int which = o >> 8;
            const int head  = (o >> 5) & 7;
            const int d     = o & 31;
            __half* dst = (which == 0) ? g_q : (which == 1 ? g_k : g_v);
            const float sc = (which == 0) ? QSCALE : 1.0f;
            const __half2 h01 = __halves2half2(__float2half_rn((v.x + bv) * sc),
                                               __float2half_rn((v.y + bv) * sc));
            const __half2 h23 = __halves2half2(__float2half_rn((v.z + bv) * sc),
                                               __float2half_rn((v.w + bv) * sc));
            const size_t off =
                ((size_t)(((b_ * 8 + head) * 16 + t_) * 32 + d)) * 1024 + hw0 + lane * 4;
            uint2 pk;
            pk.x = *(const uint32_t*)&h01;
            pk.y = *(const uint32_t*)&h23;
            *(uint2*)(dst + off) = pk;
        } else {
            v.x += bv; v.y += bv; v.z += bv; v.w += bv;
            *(float4*)(Y + ((size_t)slab * 256 + o) * 1024 + hw0 + lane * 4) = v;
        }
    }
}

// ================= fused prep kernel =================
// blocks [0,768):    w_qkv fp16 convert (row = bid, 256 elems)
// blocks [768,1024): w_out fp16 convert
// blocks [1024,5120): x [slab][c][hw] -> g_xhi [slab][hw][c] fp16 (64x64 tiles)
__global__ __launch_bounds__(256) void prep_k(const float* __restrict__ w_qkv,
                                              const float* __restrict__ w_out,
                                              const float* __restrict__ x) {
    const int bid = blockIdx.x;
    const int tid = threadIdx.x;

    if (bid < 768) {
        const int i = bid * 256 + tid;
        g_whi[i] = __float2half_rn(w_qkv[i]);
        return;
    }
    if (bid < 1024) {
        const int i = (bid - 768) * 256 + tid;
        g_wohi[i] = __float2half_rn(w_out[i]);
        return;
    }

    __shared__ float ts[64][65];
    const int id = bid - 1024;
    const int h0 = (id & 15) * 64;
    const int c0 = ((id >> 4) & 3) * 64;
    const int slab = id >> 6;
    const int r = tid >> 2;
    const int q4 = tid & 3;

    const float* src = x + ((size_t)slab * 256 + c0 + r) * 1024 + h0 + q4 * 16;
#pragma unroll
    for (int j = 0; j < 4; j++) {
        const float4 v = *(const float4*)(src + j * 4);
        ts[r][q4 * 16 + j * 4 + 0] = v.x;
        ts[r][q4 * 16 + j * 4 + 1] = v.y;
        ts[r][q4 * 16 + j * 4 + 2] = v.z;
        ts[r][q4 * 16 + j * 4 + 3] = v.w;
    }
    __syncthreads();

    __half hb[16];
#pragma unroll
    for (int j = 0; j < 16; j++)
        hb[j] = __float2half_rn(ts[q4 * 16 + j][r]);
    const size_t o = ((size_t)slab * 1024 + h0 + r) * 256 + c0 + q4 * 16;
    *(uint4*)(g_xhi + o)     = ((uint4*)hb)[0];
    *(uint4*)(g_xhi + o + 8) = ((uint4*)hb)[1];
}

// ================= attention (T=16), fp16 in, fp16 out =================
__device__ __forceinline__ unsigned long long pack2(float lo, float hi) {
    unsigned long long r;
    asm("mov.b64 %0, {%1, %2};" : "=l"(r) : "f"(lo), "f"(hi));
    return r;
}
__device__ __forceinline__ void unpack2(unsigned long long p, float& lo, float& hi) {
    asm("mov.b64 {%0, %1}, %2;" : "=f"(lo), "=f"(hi) : "l"(p));
}
__device__ __forceinline__ unsigned long long ffma2(unsigned long long a,
                                                    unsigned long long b,
                                                    unsigned long long c) {
    unsigned long long d;
    asm("fma.rn.f32x2 %0, %1, %2, %3;" : "=l"(d) : "l"(a), "l"(b), "l"(c));
    return d;
}

constexpr int KVP = 516;
constexpr int ATTN_SMEM = 2 * 16 * KVP * 4;   // 66048 bytes

__global__ __launch_bounds__(256) void attn_k(const float* __restrict__ rel_pos) {
    extern __shared__ __align__(16) float asmem[];
    float* k_s = asmem;                 // [16][KVP]
    float* v_s = asmem + 16 * KVP;

    const int bh  = blockIdx.y;            // b*8 + head
    const int hw0 = blockIdx.x * 16;
    const int tid = threadIdx.x;
    const int hwl = tid & 15;
    const int i   = tid >> 4;              // query t 0..15

    const size_t ubase = (size_t)bh * 512 * HW;

#pragma unroll
    for (int it = 0; it < 4; it++) {
        const int slot = tid + 256 * it;   // 0..1023
        const int td  = slot >> 1;
        const int seg = (slot & 1) * 8;
        const size_t go = ubase + (size_t)td * HW + hw0 + seg;
        const uint4 rk = *(const uint4*)(g_k + go);
        const uint4 rv = *(const uint4*)(g_v + go);
        const __half2* hk = (const __half2*)&rk;
        const __half2* hv = (const __half2*)&rv;
#pragma unroll
        for (int c = 0; c < 4; c++) {
            const float2 fk = __half22float2(hk[c]);
            const float2 fv = __half22float2(hv[c]);
            k_s[(seg + 2 * c)     * KVP + td] = fk.x;
            k_s[(seg + 2 * c + 1) * KVP + td] = fk.y;
            v_s[(seg + 2 * c)     * KVP + td] = fv.x;
            v_s[(seg + 2 * c + 1) * KVP + td] = fv.y;
        }
    }
    __syncthreads();

    unsigned long long qp[16];
    const size_t qbase = ubase + (size_t)i * 32 * HW + hw0 + hwl;
#pragma unroll
    for (int c = 0; c < 16; c++)
        qp[c] = pack2(__half2float(g_q[qbase + (size_t)(2 * c) * HW]),
                      __half2float(g_q[qbase + (size_t)(2 * c + 1) * HW]));

    const int head = bh & 7;
    const float* rp = rel_pos + head * 256 + i * 16;

    float s[16];
#pragma unroll
    for (int j = 0; j < 16; j++) {
        const ulonglong2* kp = (const ulonglong2*)&k_s[hwl * KVP + j * 32];
        unsigned long long acc = 0ull;
#pragma unroll
        for (int c = 0; c < 8; c++) {
            const ulonglong2 kk = kp[c];
            acc = ffma2(qp[2 * c],     kk.x, acc);
            acc = ffma2(qp[2 * c + 1], kk.y, acc);
        }
        float lo, hi;
        unpack2(acc, lo, hi);
        s[j] = lo + hi + rp[j];
    }

    float mx = s[0];
#pragma unroll
    for (int j = 1; j < 16; j++) mx = fmaxf(mx, s[j]);
    float sum = 0.0f;
#pragma unroll
    for (int j = 0; j < 16; j++) { s[j] = expf(s[j] - mx); sum += s[j]; }
    const float inv = 1.0f / sum;

    unsigned long long o2[16];
#pragma unroll
    for (int c = 0; c < 16; c++) o2[c] = 0ull;
#pragma unroll
    for (int j = 0; j < 16; j++) {
        const unsigned long long pp = pack2(s[j], s[j]);
        const ulonglong2* vp = (const ulonglong2*)&v_s[hwl * KVP + j * 32];
#pragma unroll
        for (int c = 0; c < 8; c++) {
            const ulonglong2 vv = vp[c];
            o2[2 * c]     = ffma2(pp, vv.x, o2[2 * c]);
            o2[2 * c + 1] = ffma2(pp, vv.y, o2[2 * c + 1]);
        }
    }

    const int b_ = bh >> 3;
    const size_t obase =
        ((size_t)((b_ * 16 + i)) * 1024 + hw0 + hwl) * 256 + head * 32;
#pragma unroll
    for (int c = 0; c < 16; c++) {
        float lo, hi;
        unpack2(o2[c], lo, hi);
        ((__half2*)(g_ohi + obase))[c] =
            __halves2half2(__float2half_rn(lo * inv), __float2half_rn(hi * inv));
    }
}

// ================= host =================
extern "C" void kernel_launch(void* const* d_in, const int* in_sizes, int n_in,
                              void* d_out, int out_size) {
    const float* x       = (const float*)d_in[0];
    const float* rel_pos = (const float*)d_in[1];
    const float* w_qkv   = (const float*)d_in[2];
    const float* b_qkv   = (const float*)d_in[3];
    const float* w_out   = (const float*)d_in[4];
    const float* b_out   = (const float*)d_in[5];
    float* y = (float*)d_out;

    cudaFuncSetAttribute(mma_gemm<0>, cudaFuncAttributeMaxDynamicSharedMemorySize, SMEM_TOTAL);
    cudaFuncSetAttribute(mma_gemm<1>, cudaFuncAttributeMaxDynamicSharedMemorySize, SMEM_TOTAL);
    cudaFuncSetAttribute(attn_k, cudaFuncAttributeMaxDynamicSharedMemorySize, ATTN_SMEM);

    __half *xhi, *whi, *wohi, *ohi;
    cudaGetSymbolAddress((void**)&xhi, g_xhi);
    cudaGetSymbolAddress((void**)&whi, g_whi);
    cudaGetSymbolAddress((void**)&wohi, g_wohi);
    cudaGetSymbolAddress((void**)&ohi, g_ohi);

    // fused prep: weight converts + x transpose/convert (one launch)
    prep_k<<<5120, 256>>>(w_qkv, w_out, x);
    // QKV projection (single fp16 pass, BK=64): grid = (hw 8, o 12, slabs 64)
    mma_gemm<0><<<dim3(8, 12, 64), 128, SMEM_TOTAL>>>(xhi, whi, b_qkv, nullptr);
    // attention: grid = (hw tiles 64, b*heads 32), 256 threads
    attn_k<<<dim3(64, 32), 256, ATTN_SMEM>>>(rel_pos);
    // output projection (single fp16 pass): grid = (8, 4, 64)
    mma_gemm<1><<<dim3(8, 4, 64), 128, SMEM_TOTAL>>>(ohi, wohi, b_out, y);
}

// round 17
// speedup vs baseline: 1.7154x; 1.1799x over previous
#include <cuda_runtime.h>
#include <cuda_fp16.h>
#include <cstdint>

// ---------------- problem constants ----------------
constexpr int B_    = 4;
constexpr int T_    = 16;
constexpr int HEADS = 8;
constexpr int HW    = 1024;       // 32*32
constexpr int NSLAB = B_ * T_;    // 64
constexpr float QSCALE = 0.17677669529663687f;

// ---------------- scratch (__device__ globals) ----------------
__device__ __half g_x16[NSLAB * 256 * HW];  // [slab][c][hw]  (natural layout)
__device__ __half g_w16[768 * 256];         // [o][c]
__device__ __half g_wo16[256 * 256];
__device__ __half g_q[B_ * HEADS * T_ * 32 * HW];  // fp16 [b][head][t][d][hw]
__device__ __half g_k[B_ * HEADS * T_ * 32 * HW];
__device__ __half g_v[B_ * HEADS * T_ * 32 * HW];
__device__ __half g_o16[NSLAB * 256 * HW];  // [slab][e][hw]

// ---------------- PTX helpers ----------------
__device__ __forceinline__ uint32_t smem_u32(const void* p) {
    uint32_t a;
    asm("{ .reg .u64 t; cvta.to.shared.u64 t, %1; cvt.u32.u64 %0, t; }" : "=r"(a) : "l"(p));
    return a;
}
__device__ __forceinline__ void cp16(uint32_t s, const void* g) {
    asm volatile("cp.async.cg.shared.global [%0], [%1], 16;" :: "r"(s), "l"(g) : "memory");
}
__device__ __forceinline__ void cp_commit() {
    asm volatile("cp.async.commit_group;" ::: "memory");
}
template <int N>
__device__ __forceinline__ void cp_wait() {
    asm volatile("cp.async.wait_group %0;" :: "n"(N) : "memory");
}
__device__ __forceinline__ void ldsm4(uint32_t& r0, uint32_t& r1, uint32_t& r2,
                                      uint32_t& r3, uint32_t a) {
    asm volatile("ldmatrix.sync.aligned.m8n8.x4.shared.b16 {%0,%1,%2,%3}, [%4];"
                 : "=r"(r0), "=r"(r1), "=r"(r2), "=r"(r3) : "r"(a));
}
__device__ __forceinline__ void ldsm4t(uint32_t& r0, uint32_t& r1, uint32_t& r2,
                                       uint32_t& r3, uint32_t a) {
    asm volatile("ldmatrix.sync.aligned.m8n8.x4.trans.shared.b16 {%0,%1,%2,%3}, [%4];"
                 : "=r"(r0), "=r"(r1), "=r"(r2), "=r"(r3) : "r"(a));
}
__device__ __forceinline__ void mma16816(float& c0, float& c1, float& c2, float& c3,
                                         uint32_t a0, uint32_t a1, uint32_t a2,
                                         uint32_t a3, uint32_t b0, uint32_t b1) {
    asm volatile(
        "mma.sync.aligned.m16n8k16.row.col.f32.f16.f16.f32 "
        "{%0,%1,%2,%3}, {%4,%5,%6,%7}, {%8,%9}, {%0,%1,%2,%3};"
        : "+f"(c0), "+f"(c1), "+f"(c2), "+f"(c3)
        : "r"(a0), "r"(a1), "r"(a2), "r"(a3), "r"(b0), "r"(b1));
}

// ---------------- SMEM staging layout (BK=64) ----------------
// A (W): 64 o-rows x 64 halves = 128B rows (8 chunks), chunk^(row&7) swizzle.
// B (X): 64 c-rows x 128 hw halves = 256B rows (16 chunks), same swizzle.
constexpr int O_A   = 0;            // 8 KB
constexpr int O_B   = 8192;         // 16 KB
constexpr int STAGE = 24576;
constexpr int SMEM_TOTAL = 49152;   // 2 stages

// ================= tensor-core GEMM (D[o][hw]) =================
// D[m=o 64][n=hw 128] = W[o,K] * X[K,hw], K=256, single fp16 pass.
// 128 threads, 4 warps (2m x 2n), warp tile 32(o) x 64(hw), BK=64,
// 2-stage cp.async, 4 CTAs/SM. B fragments via ldmatrix.trans from the
// NATURAL [c][hw] layout -> no transposes anywhere in the pipeline.
// EPI 0: q/k/v fp16 rows [d][hw]. EPI 1: +bias -> f32 Y [c][hw].
template <int EPI>
__global__ __launch_bounds__(128, 4) void mma_gemm(const __half* __restrict__ Xc,
                                                   const __half* __restrict__ W,
                                                   const float* __restrict__ bias,
                                                   float* __restrict__ Y) {
    extern __shared__ __align__(1024) char smem[];
    __shared__ float bs[64];
    const uint32_t sb = smem_u32(smem);
    const int tid  = threadIdx.x;
    const int wid  = tid >> 5;
    const int lane = tid & 31;
    const int wm = wid & 1;     // o half (32 rows)
    const int wn = wid >> 1;    // hw half (64 cols)

    const int slab = blockIdx.z;
    const int hw0  = blockIdx.x * 128;
    const int n0   = blockIdx.y * 64;   // o-tile base

    if (tid < 64) bs[tid] = bias[n0 + tid];

    const __half* wsrc = W + (size_t)n0 * 256;
    const __half* xsrc = Xc + (size_t)slab * 256 * HW + hw0;

    // ---- ldmatrix base addresses (kk=0, stage 0) ----
    // A (non-trans): rows m, chunk = 2kk + (lane>>4), swizzle ^(lane&7).
    const uint32_t achfix = (uint32_t)(((lane >> 4) ^ (lane & 7)) << 4);
    const uint32_t adrA[2] = {
        sb + O_A + (uint32_t)((wm * 32 + (lane & 15)) * 128) + achfix,
        sb + O_A + (uint32_t)((wm * 32 + 16 + (lane & 15)) * 128) + achfix};
    // B (trans): row = kk*16 + (lane&7) + ((lane>>3)&1)*8,
    //            chunk = wn*8 + j + ((lane>>4)&1), swizzle ^(lane&7).
    const int rowB0 = (lane & 7) + ((lane >> 3) & 1) * 8;
    const uint32_t adrB = sb + O_B + (uint32_t)(rowB0 * 256) +
        (uint32_t)(((wn * 8 + ((lane >> 4) & 1)) ^ (lane & 7)) << 4);

    float acc[2][8][4];
#pragma unroll
    for (int mt = 0; mt < 2; mt++)
#pragma unroll
        for (int nt = 0; nt < 8; nt++)
#pragma unroll
            for (int r = 0; r < 4; r++) acc[mt][nt][r] = 0.0f;

    // ---- cp.async task maps ----
    const int rA = tid >> 3, cA = tid & 7;            // A: 16 rows/pass, 8 chunks
    const uint32_t offA = (uint32_t)(rA * 128 + ((cA ^ (rA & 7)) << 4));
    const int rB = tid >> 4, cB = tid & 15;           // B: 8 rows/pass, 16 chunks
    const uint32_t offB = (uint32_t)(rB * 256 + ((cB ^ (rB & 7)) << 4));

    auto issue = [&](int kt, int s) {
        const uint32_t base = sb + s * STAGE;
        const int kbase = kt * 64;
#pragma unroll
        for (int v = 0; v < 4; v++)           // A rows rA + 16v (0..63)
            cp16(base + O_A + offA + (uint32_t)(v * 2048),
                 wsrc + (size_t)(rA + 16 * v) * 256 + kbase + cA * 8);
#pragma unroll
        for (int v = 0; v < 8; v++)           // B rows rB + 8v (0..63)
            cp16(base + O_B + offB + (uint32_t)(v * 2048),
                 xsrc + (size_t)(kbase + rB + 8 * v) * HW + cB * 8);
    };

    issue(0, 0);
    cp_commit();

    uint32_t so = 0;
    for (int kt = 0; kt < 4; kt++) {
        if (kt < 3) {
            issue(kt + 1, (kt + 1) & 1);
            cp_commit();
            cp_wait<1>();
        } else {
            cp_wait<0>();
        }
        __syncthreads();

#pragma unroll
        for (int kk = 0; kk < 4; kk++) {
            uint32_t a[2][4];
#pragma unroll
            for (int mt = 0; mt < 2; mt++)
                ldsm4(a[mt][0], a[mt][1], a[mt][2], a[mt][3],
                      (adrA[mt] ^ (uint32_t)(kk << 5)) + so);
            uint32_t b0[8], b1[8];
            const uint32_t bkk = adrB + so + (uint32_t)(kk * 4096);
#pragma unroll
            for (int jj = 0; jj < 4; jj++) {
                const int j = 2 * jj;
                ldsm4t(b0[j], b1[j], b0[j + 1], b1[j + 1],
                       bkk ^ (uint32_t)(j << 4));
            }
#pragma unroll
            for (int mt = 0; mt < 2; mt++)
#pragma unroll
                for (int nt = 0; nt < 8; nt++)
                    mma16816(acc[mt][nt][0], acc[mt][nt][1], acc[mt][nt][2],
                             acc[mt][nt][3], a[mt][0], a[mt][1], a[mt][2],
                             a[mt][3], b0[nt], b1[nt]);
        }
        __syncthreads();
        so ^= (uint32_t)STAGE;
    }

    // ---------------- direct epilogue (no smem transpose) ----------------
    const int gid = lane >> 2, q = lane & 3;
    const int b_ = slab >> 4, t_ = slab & 15;
    if (EPI == 0) {
        const int which = n0 >> 8;                 // CTA-constant
        __half* dst = (which == 0) ? g_q : (which == 1 ? g_k : g_v);
        const float sc = (which == 0) ? QSCALE : 1.0f;
        const int head = ((n0 >> 5) + wm) & 7;
        const size_t hb = ((size_t)((b_ * 8 + head) * 16 + t_)) * 32 * 1024;
#pragma unroll
        for (int mt = 0; mt < 2; mt++) {
            const int d = mt * 16 + gid;
            const float bv0 = bs[wm * 32 + mt * 16 + gid];
            const float bv1 = bs[wm * 32 + mt * 16 + gid + 8];
#pragma unroll
            for (int nt = 0; nt < 8; nt++) {
                const int hwc = hw0 + wn * 64 + nt * 8 + 2 * q;
                const __half2 ha =
                    __halves2half2(__float2half_rn((acc[mt][nt][0] + bv0) * sc),
                                   __float2half_rn((acc[mt][nt][1] + bv0) * sc));
                const __half2 hbv =
                    __halves2half2(__float2half_rn((acc[mt][nt][2] + bv1) * sc),
                                   __float2half_rn((acc[mt][nt][3] + bv1) * sc));
                *(__half2*)(dst + hb + (size_t)d * 1024 + hwc) = ha;
                *(__half2*)(dst + hb + (size_t)(d + 8) * 1024 + hwc) = hbv;
            }
        }
    } else {
#pragma unroll
        for (int mt = 0; mt < 2; mt++) {
            const int m = wm * 32 + mt * 16 + gid;
            const float bv0 = bs[m];
            const float bv1 = bs[m + 8];
            const size_t rb = ((size_t)slab * 256 + n0 + m) * 1024;
#pragma unroll
            for (int nt = 0; nt < 8; nt++) {
                const int hwc = hw0 + wn * 64 + nt * 8 + 2 * q;
                float2 f0 = make_float2(acc[mt][nt][0] + bv0, acc[mt][nt][1] + bv0);
                float2 f1 = make_float2(acc[mt][nt][2] + bv1, acc[mt][nt][3] + bv1);
                *(float2*)(Y + rb + hwc) = f0;
                *(float2*)(Y + rb + 8 * 1024 + hwc) = f1;
            }
        }
    }
}

// ================= fused prep kernel (pure converts, no transpose) ==========
// blocks [0,768):    w_qkv fp16 convert
// blocks [768,1024): w_out fp16 convert
// blocks [1024,5120): x f32 -> fp16 streaming convert (same layout)
__global__ __launch_bounds__(256) void prep_k(const float* __restrict__ w_qkv,
                                              const float* __restrict__ w_out,
                                              const float* __restrict__ x) {
    const int bid = blockIdx.x;
    const int tid = threadIdx.x;

    if (bid < 768) {
        const int i = bid * 256 + tid;
        g_w16[i] = __float2half_rn(w_qkv[i]);
        return;
    }
    if (bid < 1024) {
        const int i = (bid - 768) * 256 + tid;
        g_wo16[i] = __float2half_rn(w_out[i]);
        return;
    }

    const size_t base = (size_t)(bid - 1024) * 4096;
#pragma unroll
    for (int j = 0; j < 4; j++) {
        const size_t off = base + (size_t)j * 1024 + tid * 4;
        const float4 v = *(const float4*)(x + off);
        __half2 h01 = __halves2half2(__float2half_rn(v.x), __float2half_rn(v.y));
        __half2 h23 = __halves2half2(__float2half_rn(v.z), __float2half_rn(v.w));
        uint2 pk;
        pk.x = *(const uint32_t*)&h01;
        pk.y = *(const uint32_t*)&h23;
        *(uint2*)(g_x16 + off) = pk;
    }
}

// ================= attention (T=16), fp16 in, fp16 [e][hw] out ==============
__device__ __forceinline__ unsigned long long pack2(float lo, float hi) {
    unsigned long long r;
    asm("mov.b64 %0, {%1, %2};" : "=l"(r) : "f"(lo), "f"(hi));
    return r;
}
__device__ __forceinline__ void unpack2(unsigned long long p, float& lo, float& hi) {
    asm("mov.b64 {%0, %1}, %2;" : "=f"(lo), "=f"(hi) : "l"(p));
}
__device__ __forceinline__ unsigned long long ffma2(unsigned long long a,
                                                    unsigned long long b,
                                                    unsigned long long c) {
    unsigned long long d;
    asm("fma.rn.f32x2 %0, %1, %2, %3;" : "=l"(d) : "l"(a), "l"(b), "l"(c));
    return d;
}

constexpr int KVP = 516;
constexpr int ATTN_SMEM = 2 * 16 * KVP * 4;   // 66048 bytes

__global__ __launch_bounds__(256) void attn_k(const float* __restrict__ rel_pos) {
    extern __shared__ __align__(16) float asmem[];
    float* k_s = asmem;                 // [16][KVP]
    float* v_s = asmem + 16 * KVP;

    const int bh  = blockIdx.y;            // b*8 + head
    const int hw0 = blockIdx.x * 16;
    const int tid = threadIdx.x;
    const int hwl = tid & 15;
    const int i   = tid >> 4;              // query t 0..15

    const size_t ubase = (size_t)bh * 512 * HW;

#pragma unroll
    for (int it = 0; it < 4; it++) {
        const int slot = tid + 256 * it;   // 0..1023
        const int td  = slot >> 1;
        const int seg = (slot & 1) * 8;
        const size_t go = ubase + (size_t)td * HW + hw0 + seg;
        const uint4 rk = *(const uint4*)(g_k + go);
        const uint4 rv = *(const uint4*)(g_v + go);
        const __half2* hk = (const __half2*)&rk;
        const __half2* hv = (const __half2*)&rv;
#pragma unroll
        for (int c = 0; c < 4; c++) {
            const float2 fk = __half22float2(hk[c]);
            const float2 fv = __half22float2(hv[c]);
            k_s[(seg + 2 * c)     * KVP + td] = fk.x;
            k_s[(seg + 2 * c + 1) * KVP + td] = fk.y;
            v_s[(seg + 2 * c)     * KVP + td] = fv.x;
            v_s[(seg + 2 * c + 1) * KVP + td] = fv.y;
        }
    }
    __syncthreads();

    unsigned long long qp[16];
    const size_t qbase = ubase + (size_t)i * 32 * HW + hw0 + hwl;
#pragma unroll
    for (int c = 0; c < 16; c++)
        qp[c] = pack2(__half2float(g_q[qbase + (size_t)(2 * c) * HW]),
                      __half2float(g_q[qbase + (size_t)(2 * c + 1) * HW]));

    const int head = bh & 7;
    const float* rp = rel_pos + head * 256 + i * 16;

    float s[16];
#pragma unroll
    for (int j = 0; j < 16; j++) {
        const ulonglong2* kp = (const ulonglong2*)&k_s[hwl * KVP + j * 32];
        unsigned long long acc = 0ull;
#pragma unroll
        for (int c = 0; c < 8; c++) {
            const ulonglong2 kk = kp[c];
            acc = ffma2(qp[2 * c],     kk.x, acc);
            acc = ffma2(qp[2 * c + 1], kk.y, acc);
        }
        float lo, hi;
        unpack2(acc, lo, hi);
        s[j] = lo + hi + rp[j];
    }

    float mx = s[0];
#pragma unroll
    for (int j = 1; j < 16; j++) mx = fmaxf(mx, s[j]);
    float sum = 0.0f;
#pragma unroll
    for (int j = 0; j < 16; j++) { s[j] = expf(s[j] - mx); sum += s[j]; }
    const float inv = 1.0f / sum;

    unsigned long long o2[16];
#pragma unroll
    for (int c = 0; c < 16; c++) o2[c] = 0ull;
#pragma unroll
    for (int j = 0; j < 16; j++) {
        const unsigned long long pp = pack2(s[j], s[j]);
        const ulonglong2* vp = (const ulonglong2*)&v_s[hwl * KVP + j * 32];
#pragma unroll
        for (int c = 0; c < 8; c++) {
            const ulonglong2 vv = vp[c];
            o2[2 * c]     = ffma2(pp, vv.x, o2[2 * c]);
            o2[2 * c + 1] = ffma2(pp, vv.y, o2[2 * c + 1]);
        }
    }

    // write fp16 output [slab][e][hw] (natural for the D[o][hw] gemm)
    const int b_ = bh >> 3;
    const size_t obase =
        ((size_t)(b_ * 16 + i) * 256 + head * 32) * 1024 + hw0 + hwl;
#pragma unroll
    for (int c = 0; c < 16; c++) {
        float lo, hi;
        unpack2(o2[c], lo, hi);
        g_o16[obase + (size_t)(2 * c) * 1024]     = __float2half_rn(lo * inv);
        g_o16[obase + (size_t)(2 * c + 1) * 1024] = __float2half_rn(hi * inv);
    }
}

// ================= host =================
extern "C" void kernel_launch(void* const* d_in, const int* in_sizes, int n_in,
                              void* d_out, int out_size) {
    const float* x       = (const float*)d_in[0];
    const float* rel_pos = (const float*)d_in[1];
    const float* w_qkv   = (const float*)d_in[2];
    const float* b_qkv   = (const float*)d_in[3];
    const float* w_out   = (const float*)d_in[4];
    const float* b_out   = (const float*)d_in[5];
    float* y = (float*)d_out;

    cudaFuncSetAttribute(mma_gemm<0>, cudaFuncAttributeMaxDynamicSharedMemorySize, SMEM_TOTAL);
    cudaFuncSetAttribute(mma_gemm<1>, cudaFuncAttributeMaxDynamicSharedMemorySize, SMEM_TOTAL);
    cudaFuncSetAttribute(attn_k, cudaFuncAttributeMaxDynamicSharedMemorySize, ATTN_SMEM);

    __half *x16, *w16, *wo16, *o16;
    cudaGetSymbolAddress((void**)&x16, g_x16);
    cudaGetSymbolAddress((void**)&w16, g_w16);
    cudaGetSymbolAddress((void**)&wo16, g_wo16);
    cudaGetSymbolAddress((void**)&o16, g_o16);

    // fused prep: pure fp16 converts (no transpose, no smem)
    prep_k<<<5120, 256>>>(w_qkv, w_out, x);
    // QKV projection: D[o][hw], grid = (hw 8, o-tiles 12, slabs 64)
    mma_gemm<0><<<dim3(8, 12, 64), 128, SMEM_TOTAL>>>(x16, w16, b_qkv, nullptr);
    // attention: grid = (hw tiles 64, b*heads 32), 256 threads
    attn_k<<<dim3(64, 32), 256, ATTN_SMEM>>>(rel_pos);
    // output projection: D[c][hw] -> y directly, grid = (8, 4, 64)
    mma_gemm<1><<<dim3(8, 4, 64), 128, SMEM_TOTAL>>>(o16, wo16, b_out, y);
}